// round 1
// baseline (speedup 1.0000x reference)
#include <cuda_runtime.h>

#define D_IN  128
#define HID   512
#define D_OUTK 128
#define NOBJ  100000
#define NT    200000

#define BM 128
#define BN 128
#define BK 32

// Scratch (device globals — no allocation allowed)
__device__ __align__(16) float g_h[(size_t)NT * HID];        // 409.6 MB
__device__ __align__(16) float g_pooled[(size_t)NOBJ * HID]; // 204.8 MB
__device__ __align__(16) float g_tmp[(size_t)NOBJ * HID];    // 204.8 MB
__device__ __align__(16) float g_counts[NOBJ];

// ---------------------------------------------------------------------------
__global__ void zero_kernel() {
    int i = blockIdx.x * blockDim.x + threadIdx.x;
    float4 z = make_float4(0.f, 0.f, 0.f, 0.f);
    if (i < (NOBJ * HID) / 4) ((float4*)g_pooled)[i] = z;
    if (i < NOBJ / 4)         ((float4*)g_counts)[i] = z;
}

__global__ void count_kernel(const int* __restrict__ edges) {
    int t = blockIdx.x * blockDim.x + threadIdx.x;
    if (t < NT) {
        atomicAdd(&g_counts[edges[2 * t]],     1.f);
        atomicAdd(&g_counts[edges[2 * t + 1]], 1.f);
    }
}

// ---------------------------------------------------------------------------
// GEMM1: h = relu(concat(obj[s], pred, obj[o]) @ W1 + b1)
// M = NT, K = 384, N = 512. Gather fused into A-tile load.
__global__ __launch_bounds__(256) void gemm1_gather(
    const float* __restrict__ obj, const float* __restrict__ pred,
    const int* __restrict__ edges, const float* __restrict__ W1,
    const float* __restrict__ b1, int M)
{
    const int K = 3 * D_IN, N = HID;
    __shared__ float As[BK][BM];
    __shared__ float Bs[BK][BN];

    int tid = threadIdx.x;
    int tx = tid & 15, ty = tid >> 4;
    int row0 = blockIdx.y * BM, col0 = blockIdx.x * BN;

    float acc[8][8];
#pragma unroll
    for (int i = 0; i < 8; i++)
#pragma unroll
        for (int j = 0; j < 8; j++) acc[i][j] = 0.f;

    for (int k0 = 0; k0 < K; k0 += BK) {
#pragma unroll
        for (int i = 0; i < 4; ++i) {
            int f = tid + i * 256;
            int m = f >> 3;
            int kk = (f & 7) << 2;
            int mg = row0 + m;
            float4 v = make_float4(0.f, 0.f, 0.f, 0.f);
            if (mg < M) {
                int gk = k0 + kk;
                const float* src;
                if (gk < 128)      src = obj  + (size_t)edges[2 * mg]     * 128 + gk;
                else if (gk < 256) src = pred + (size_t)mg                * 128 + (gk - 128);
                else               src = obj  + (size_t)edges[2 * mg + 1] * 128 + (gk - 256);
                v = *(const float4*)src;
            }
            As[kk + 0][m] = v.x; As[kk + 1][m] = v.y;
            As[kk + 2][m] = v.z; As[kk + 3][m] = v.w;
        }
#pragma unroll
        for (int i = 0; i < 4; ++i) {
            int f = tid + i * 256;
            int kk = f >> 5;
            int n = (f & 31) << 2;
            *(float4*)&Bs[kk][n] = *(const float4*)&W1[(size_t)(k0 + kk) * N + col0 + n];
        }
        __syncthreads();
#pragma unroll 8
        for (int k = 0; k < BK; ++k) {
            float a[8], b[8];
            *(float4*)&a[0] = *(const float4*)&As[k][ty * 8];
            *(float4*)&a[4] = *(const float4*)&As[k][ty * 8 + 4];
            *(float4*)&b[0] = *(const float4*)&Bs[k][tx * 8];
            *(float4*)&b[4] = *(const float4*)&Bs[k][tx * 8 + 4];
#pragma unroll
            for (int i = 0; i < 8; i++)
#pragma unroll
                for (int j = 0; j < 8; j++)
                    acc[i][j] = fmaf(a[i], b[j], acc[i][j]);
        }
        __syncthreads();
    }

    float bb[8];
#pragma unroll
    for (int j = 0; j < 8; j++) bb[j] = b1[col0 + tx * 8 + j];
#pragma unroll
    for (int i = 0; i < 8; i++) {
        int mg = row0 + ty * 8 + i;
        if (mg < M) {
            float4 v0, v1;
            v0.x = fmaxf(acc[i][0] + bb[0], 0.f);
            v0.y = fmaxf(acc[i][1] + bb[1], 0.f);
            v0.z = fmaxf(acc[i][2] + bb[2], 0.f);
            v0.w = fmaxf(acc[i][3] + bb[3], 0.f);
            v1.x = fmaxf(acc[i][4] + bb[4], 0.f);
            v1.y = fmaxf(acc[i][5] + bb[5], 0.f);
            v1.z = fmaxf(acc[i][6] + bb[6], 0.f);
            v1.w = fmaxf(acc[i][7] + bb[7], 0.f);
            float* dst = &g_h[(size_t)mg * HID + col0 + tx * 8];
            *(float4*)dst = v0;
            *(float4*)(dst + 4) = v1;
        }
    }
}

// ---------------------------------------------------------------------------
// GEMM2: new_t = relu(h @ W2 + b2), N = 1152.
// Cols [0,512)  -> atomicAdd into pooled[s_idx]
// Cols [512,640)-> new_p output
// Cols [640,1152)->atomicAdd into pooled[o_idx]
__global__ __launch_bounds__(256) void gemm2_scatter(
    const float* __restrict__ W2, const float* __restrict__ b2,
    const int* __restrict__ edges, float* __restrict__ out_p, int M)
{
    const int K = HID, N = 2 * HID + D_OUTK; // 1152
    __shared__ float As[BK][BM];
    __shared__ float Bs[BK][BN];

    int tid = threadIdx.x;
    int tx = tid & 15, ty = tid >> 4;
    int row0 = blockIdx.y * BM, col0 = blockIdx.x * BN;

    float acc[8][8];
#pragma unroll
    for (int i = 0; i < 8; i++)
#pragma unroll
        for (int j = 0; j < 8; j++) acc[i][j] = 0.f;

    for (int k0 = 0; k0 < K; k0 += BK) {
#pragma unroll
        for (int i = 0; i < 4; ++i) {
            int f = tid + i * 256;
            int m = f >> 3;
            int kk = (f & 7) << 2;
            int mg = row0 + m;
            float4 v = make_float4(0.f, 0.f, 0.f, 0.f);
            if (mg < M) v = *(const float4*)&g_h[(size_t)mg * K + k0 + kk];
            As[kk + 0][m] = v.x; As[kk + 1][m] = v.y;
            As[kk + 2][m] = v.z; As[kk + 3][m] = v.w;
        }
#pragma unroll
        for (int i = 0; i < 4; ++i) {
            int f = tid + i * 256;
            int kk = f >> 5;
            int n = (f & 31) << 2;
            *(float4*)&Bs[kk][n] = *(const float4*)&W2[(size_t)(k0 + kk) * N + col0 + n];
        }
        __syncthreads();
#pragma unroll 8
        for (int k = 0; k < BK; ++k) {
            float a[8], b[8];
            *(float4*)&a[0] = *(const float4*)&As[k][ty * 8];
            *(float4*)&a[4] = *(const float4*)&As[k][ty * 8 + 4];
            *(float4*)&b[0] = *(const float4*)&Bs[k][tx * 8];
            *(float4*)&b[4] = *(const float4*)&Bs[k][tx * 8 + 4];
#pragma unroll
            for (int i = 0; i < 8; i++)
#pragma unroll
                for (int j = 0; j < 8; j++)
                    acc[i][j] = fmaf(a[i], b[j], acc[i][j]);
        }
        __syncthreads();
    }

    float bb[8];
#pragma unroll
    for (int j = 0; j < 8; j++) bb[j] = b2[col0 + tx * 8 + j];

    int mode = (col0 < HID) ? 0 : ((col0 < HID + D_OUTK) ? 1 : 2);

#pragma unroll
    for (int i = 0; i < 8; i++) {
        int mg = row0 + ty * 8 + i;
        if (mg >= M) continue;
        if (mode == 0) {
            int s = edges[2 * mg];
            float* dst = &g_pooled[(size_t)s * HID + col0 + tx * 8];
#pragma unroll
            for (int j = 0; j < 8; j++)
                atomicAdd(&dst[j], fmaxf(acc[i][j] + bb[j], 0.f));
        } else if (mode == 1) {
            float4 v0, v1;
            v0.x = fmaxf(acc[i][0] + bb[0], 0.f);
            v0.y = fmaxf(acc[i][1] + bb[1], 0.f);
            v0.z = fmaxf(acc[i][2] + bb[2], 0.f);
            v0.w = fmaxf(acc[i][3] + bb[3], 0.f);
            v1.x = fmaxf(acc[i][4] + bb[4], 0.f);
            v1.y = fmaxf(acc[i][5] + bb[5], 0.f);
            v1.z = fmaxf(acc[i][6] + bb[6], 0.f);
            v1.w = fmaxf(acc[i][7] + bb[7], 0.f);
            float* dst = &out_p[(size_t)mg * D_OUTK + (col0 - HID) + tx * 8];
            *(float4*)dst = v0;
            *(float4*)(dst + 4) = v1;
        } else {
            int o = edges[2 * mg + 1];
            float* dst = &g_pooled[(size_t)o * HID + (col0 - HID - D_OUTK) + tx * 8];
#pragma unroll
            for (int j = 0; j < 8; j++)
                atomicAdd(&dst[j], fmaxf(acc[i][j] + bb[j], 0.f));
        }
    }
}

// ---------------------------------------------------------------------------
// stage 0: tmp     = relu((pooled / max(counts,1)) @ W3 + b3)   (N=512)
// stage 1: new_obj = relu(tmp @ W4 + b4)                        (N=128)
__global__ __launch_bounds__(256) void gemm_plain(
    const float* __restrict__ Bmat, const float* __restrict__ bias,
    float* __restrict__ Cout, int M, int N, int stage)
{
    const int K = HID;
    __shared__ float As[BK][BM];
    __shared__ float Bs[BK][BN];

    int tid = threadIdx.x;
    int tx = tid & 15, ty = tid >> 4;
    int row0 = blockIdx.y * BM, col0 = blockIdx.x * BN;

    const float* A = (stage == 0) ? g_pooled : g_tmp;
    float* C = (stage == 0) ? g_tmp : Cout;

    float acc[8][8];
#pragma unroll
    for (int i = 0; i < 8; i++)
#pragma unroll
        for (int j = 0; j < 8; j++) acc[i][j] = 0.f;

    for (int k0 = 0; k0 < K; k0 += BK) {
#pragma unroll
        for (int i = 0; i < 4; ++i) {
            int f = tid + i * 256;
            int m = f >> 3;
            int kk = (f & 7) << 2;
            int mg = row0 + m;
            float4 v = make_float4(0.f, 0.f, 0.f, 0.f);
            if (mg < M) {
                v = *(const float4*)&A[(size_t)mg * K + k0 + kk];
                if (stage == 0) {
                    float sc = 1.f / fmaxf(g_counts[mg], 1.f);
                    v.x *= sc; v.y *= sc; v.z *= sc; v.w *= sc;
                }
            }
            As[kk + 0][m] = v.x; As[kk + 1][m] = v.y;
            As[kk + 2][m] = v.z; As[kk + 3][m] = v.w;
        }
#pragma unroll
        for (int i = 0; i < 4; ++i) {
            int f = tid + i * 256;
            int kk = f >> 5;
            int n = (f & 31) << 2;
            *(float4*)&Bs[kk][n] = *(const float4*)&Bmat[(size_t)(k0 + kk) * N + col0 + n];
        }
        __syncthreads();
#pragma unroll 8
        for (int k = 0; k < BK; ++k) {
            float a[8], b[8];
            *(float4*)&a[0] = *(const float4*)&As[k][ty * 8];
            *(float4*)&a[4] = *(const float4*)&As[k][ty * 8 + 4];
            *(float4*)&b[0] = *(const float4*)&Bs[k][tx * 8];
            *(float4*)&b[4] = *(const float4*)&Bs[k][tx * 8 + 4];
#pragma unroll
            for (int i = 0; i < 8; i++)
#pragma unroll
                for (int j = 0; j < 8; j++)
                    acc[i][j] = fmaf(a[i], b[j], acc[i][j]);
        }
        __syncthreads();
    }

    float bb[8];
#pragma unroll
    for (int j = 0; j < 8; j++) bb[j] = bias[col0 + tx * 8 + j];
#pragma unroll
    for (int i = 0; i < 8; i++) {
        int mg = row0 + ty * 8 + i;
        if (mg < M) {
            float4 v0, v1;
            v0.x = fmaxf(acc[i][0] + bb[0], 0.f);
            v0.y = fmaxf(acc[i][1] + bb[1], 0.f);
            v0.z = fmaxf(acc[i][2] + bb[2], 0.f);
            v0.w = fmaxf(acc[i][3] + bb[3], 0.f);
            v1.x = fmaxf(acc[i][4] + bb[4], 0.f);
            v1.y = fmaxf(acc[i][5] + bb[5], 0.f);
            v1.z = fmaxf(acc[i][6] + bb[6], 0.f);
            v1.w = fmaxf(acc[i][7] + bb[7], 0.f);
            float* dst = &C[(size_t)mg * N + col0 + tx * 8];
            *(float4*)dst = v0;
            *(float4*)(dst + 4) = v1;
        }
    }
}

// ---------------------------------------------------------------------------
extern "C" void kernel_launch(void* const* d_in, const int* in_sizes, int n_in,
                              void* d_out, int out_size)
{
    const float* obj   = (const float*)d_in[0];
    const float* pred  = (const float*)d_in[1];
    const int*   edges = (const int*)  d_in[2];
    const float* W1 = (const float*)d_in[3];
    const float* b1 = (const float*)d_in[4];
    const float* W2 = (const float*)d_in[5];
    const float* b2 = (const float*)d_in[6];
    const float* W3 = (const float*)d_in[7];
    const float* b3 = (const float*)d_in[8];
    const float* W4 = (const float*)d_in[9];
    const float* b4 = (const float*)d_in[10];

    float* out     = (float*)d_out;
    float* out_obj = out;                           // (NOBJ, 128)
    float* out_p   = out + (size_t)NOBJ * D_OUTK;   // (NT, 128)

    int gy_t = (NT + BM - 1) / BM;   // 1563
    int gy_o = (NOBJ + BM - 1) / BM; // 782

    zero_kernel<<<(NOBJ * HID / 4 + 255) / 256, 256>>>();
    count_kernel<<<(NT + 255) / 256, 256>>>(edges);
    gemm1_gather<<<dim3(HID / BN, gy_t), 256>>>(obj, pred, edges, W1, b1, NT);
    gemm2_scatter<<<dim3((2 * HID + D_OUTK) / BN, gy_t), 256>>>(W2, b2, edges, out_p, NT);
    gemm_plain<<<dim3(HID / BN, gy_o), 256>>>(W3, b3, nullptr, NOBJ, HID, 0);
    gemm_plain<<<dim3(D_OUTK / BN, gy_o), 256>>>(W4, b4, out_obj, NOBJ, D_OUTK, 1);
}

// round 2
// speedup vs baseline: 2.7380x; 2.7380x over previous
#include <cuda_runtime.h>
#include <cstdint>

#define D_IN   128
#define HID    512
#define D_OUTK 128
#define NOBJ   100000
#define NT     200000

#define BM 128
#define BN 128
#define BK 32
#define APITCH 44    // floats; 44%32=12 -> conflict-free A frag LDS; 176B row = 16B aligned
#define BPITCH 136   // floats; 136%32=8 -> conflict-free B frag LDS; 544B row = 16B aligned

// Scratch (device globals — no allocation allowed)
__device__ __align__(16) float g_h[(size_t)NT * HID];
__device__ __align__(16) float g_pooled[(size_t)NOBJ * HID];
__device__ __align__(16) float g_tmp[(size_t)NOBJ * HID];
__device__ __align__(16) float g_counts[NOBJ];

// ---------------------------------------------------------------------------
__global__ void zero_kernel() {
    int i = blockIdx.x * blockDim.x + threadIdx.x;
    float4 z = make_float4(0.f, 0.f, 0.f, 0.f);
    if (i < (NOBJ * HID) / 4) ((float4*)g_pooled)[i] = z;
    if (i < NOBJ / 4)         ((float4*)g_counts)[i] = z;
}

__global__ void count_kernel(const int* __restrict__ edges) {
    int t = blockIdx.x * blockDim.x + threadIdx.x;
    if (t < NT) {
        atomicAdd(&g_counts[edges[2 * t]],     1.f);
        atomicAdd(&g_counts[edges[2 * t + 1]], 1.f);
    }
}

// ---------------------------------------------------------------------------
__device__ __forceinline__ uint32_t f2tf32(float f) {
    uint32_t u;
    asm("cvt.rna.tf32.f32 %0, %1;" : "=r"(u) : "f"(f));
    return u;
}

__device__ __forceinline__ uint4 f4_to_tf32(float4 v) {
    uint4 t;
    t.x = f2tf32(v.x); t.y = f2tf32(v.y);
    t.z = f2tf32(v.z); t.w = f2tf32(v.w);
    return t;
}

__device__ __forceinline__ void mma_tf32(float* c, const uint32_t* a, const uint32_t* b) {
    asm volatile(
        "mma.sync.aligned.m16n8k8.row.col.f32.tf32.tf32.f32 "
        "{%0,%1,%2,%3}, {%4,%5,%6,%7}, {%8,%9}, {%0,%1,%2,%3};"
        : "+f"(c[0]), "+f"(c[1]), "+f"(c[2]), "+f"(c[3])
        : "r"(a[0]), "r"(a[1]), "r"(a[2]), "r"(a[3]), "r"(b[0]), "r"(b[1]));
}

// Shared compute core: consumes As/Bs tiles, accumulates into acc[2][8][4].
// Warp layout: 8 warps as 4 (m) x 2 (n). Warp tile 32x64.
struct Frag {
    float acc[2][8][4];
    __device__ __forceinline__ void clear() {
#pragma unroll
        for (int i = 0; i < 2; i++)
#pragma unroll
            for (int j = 0; j < 8; j++)
#pragma unroll
                for (int k = 0; k < 4; k++) acc[i][j][k] = 0.f;
    }
};

__device__ __forceinline__ void mma_tile(
    Frag& fr, const uint32_t* As, const uint32_t* Bs, int wm, int wn, int lane)
{
    int gr = lane >> 2, ct = lane & 3;
#pragma unroll
    for (int k8 = 0; k8 < BK; k8 += 8) {
        uint32_t a[2][4], b[8][2];
#pragma unroll
        for (int mf = 0; mf < 2; mf++) {
            int r = wm * 32 + mf * 16 + gr;
            a[mf][0] = As[(size_t)r * APITCH + k8 + ct];
            a[mf][1] = As[(size_t)(r + 8) * APITCH + k8 + ct];
            a[mf][2] = As[(size_t)r * APITCH + k8 + ct + 4];
            a[mf][3] = As[(size_t)(r + 8) * APITCH + k8 + ct + 4];
        }
#pragma unroll
        for (int nf = 0; nf < 8; nf++) {
            int n = wn * 64 + nf * 8 + gr;
            b[nf][0] = Bs[(size_t)(k8 + ct) * BPITCH + n];
            b[nf][1] = Bs[(size_t)(k8 + ct + 4) * BPITCH + n];
        }
#pragma unroll
        for (int mf = 0; mf < 2; mf++)
#pragma unroll
            for (int nf = 0; nf < 8; nf++)
                mma_tf32(fr.acc[mf][nf], a[mf], b[nf]);
    }
}

// ---------------------------------------------------------------------------
// GEMM1: h = relu(concat(obj[s], pred, obj[o]) @ W1 + b1).  M=NT, K=384, N=512
__global__ __launch_bounds__(256) void gemm1_gather(
    const float* __restrict__ obj, const float* __restrict__ pred,
    const int* __restrict__ edges, const float* __restrict__ W1,
    const float* __restrict__ b1, int M)
{
    const int K = 3 * D_IN, N = HID;
    __shared__ uint32_t As[BM * APITCH];
    __shared__ uint32_t Bs[BK * BPITCH];

    int tid = threadIdx.x, lane = tid & 31, w = tid >> 5;
    int wm = w & 3, wn = w >> 2;
    int gr = lane >> 2, ct = lane & 3;
    int row0 = blockIdx.y * BM, col0 = blockIdx.x * BN;

    Frag fr; fr.clear();

    for (int k0 = 0; k0 < K; k0 += BK) {
#pragma unroll
        for (int i = 0; i < 4; ++i) {
            int f = tid + i * 256;
            int m = f >> 3, k4 = (f & 7) << 2;
            int mg = row0 + m;
            float4 v = make_float4(0.f, 0.f, 0.f, 0.f);
            if (mg < M) {
                int gk = k0 + k4;
                const float* src;
                if (gk < 128)      src = obj  + (size_t)edges[2 * mg]     * 128 + gk;
                else if (gk < 256) src = pred + (size_t)mg                * 128 + (gk - 128);
                else               src = obj  + (size_t)edges[2 * mg + 1] * 128 + (gk - 256);
                v = *(const float4*)src;
            }
            *(uint4*)&As[(size_t)m * APITCH + k4] = f4_to_tf32(v);
        }
#pragma unroll
        for (int i = 0; i < 4; ++i) {
            int f = tid + i * 256;
            int kk = f >> 5, n4 = (f & 31) << 2;
            float4 v = *(const float4*)&W1[(size_t)(k0 + kk) * N + col0 + n4];
            *(uint4*)&Bs[(size_t)kk * BPITCH + n4] = f4_to_tf32(v);
        }
        __syncthreads();
        mma_tile(fr, As, Bs, wm, wn, lane);
        __syncthreads();
    }

    float bb[8][2];
#pragma unroll
    for (int nf = 0; nf < 8; nf++) {
        int c = col0 + wn * 64 + nf * 8 + ct * 2;
        bb[nf][0] = b1[c]; bb[nf][1] = b1[c + 1];
    }
#pragma unroll
    for (int mf = 0; mf < 2; mf++)
#pragma unroll
        for (int half = 0; half < 2; half++) {
            int r = row0 + wm * 32 + mf * 16 + gr + half * 8;
            if (r >= M) continue;
            float* dst = &g_h[(size_t)r * HID + col0 + wn * 64];
#pragma unroll
            for (int nf = 0; nf < 8; nf++) {
                float2 o;
                o.x = fmaxf(fr.acc[mf][nf][half * 2 + 0] + bb[nf][0], 0.f);
                o.y = fmaxf(fr.acc[mf][nf][half * 2 + 1] + bb[nf][1], 0.f);
                *(float2*)&dst[nf * 8 + ct * 2] = o;
            }
        }
}

// ---------------------------------------------------------------------------
// GEMM2: new_t = relu(h @ W2 + b2). N=1152.
// cols [0,512): atomicAdd -> pooled[s]; [512,640): new_p; [640,1152): pooled[o]
__global__ __launch_bounds__(256) void gemm2_scatter(
    const float* __restrict__ W2, const float* __restrict__ b2,
    const int* __restrict__ edges, float* __restrict__ out_p, int M)
{
    const int K = HID, N = 2 * HID + D_OUTK;
    __shared__ uint32_t As[BM * APITCH];
    __shared__ uint32_t Bs[BK * BPITCH];

    int tid = threadIdx.x, lane = tid & 31, w = tid >> 5;
    int wm = w & 3, wn = w >> 2;
    int gr = lane >> 2, ct = lane & 3;
    int row0 = blockIdx.y * BM, col0 = blockIdx.x * BN;

    Frag fr; fr.clear();

    for (int k0 = 0; k0 < K; k0 += BK) {
#pragma unroll
        for (int i = 0; i < 4; ++i) {
            int f = tid + i * 256;
            int m = f >> 3, k4 = (f & 7) << 2;
            int mg = row0 + m;
            float4 v = make_float4(0.f, 0.f, 0.f, 0.f);
            if (mg < M) v = *(const float4*)&g_h[(size_t)mg * K + k0 + k4];
            *(uint4*)&As[(size_t)m * APITCH + k4] = f4_to_tf32(v);
        }
#pragma unroll
        for (int i = 0; i < 4; ++i) {
            int f = tid + i * 256;
            int kk = f >> 5, n4 = (f & 31) << 2;
            float4 v = *(const float4*)&W2[(size_t)(k0 + kk) * N + col0 + n4];
            *(uint4*)&Bs[(size_t)kk * BPITCH + n4] = f4_to_tf32(v);
        }
        __syncthreads();
        mma_tile(fr, As, Bs, wm, wn, lane);
        __syncthreads();
    }

    float bb[8][2];
#pragma unroll
    for (int nf = 0; nf < 8; nf++) {
        int c = col0 + wn * 64 + nf * 8 + ct * 2;
        bb[nf][0] = b2[c]; bb[nf][1] = b2[c + 1];
    }

    int mode = (col0 < HID) ? 0 : ((col0 < HID + D_OUTK) ? 1 : 2);

#pragma unroll
    for (int mf = 0; mf < 2; mf++)
#pragma unroll
        for (int half = 0; half < 2; half++) {
            int r = row0 + wm * 32 + mf * 16 + gr + half * 8;
            if (r >= M) continue;
            if (mode == 0) {
                int s = edges[2 * r];
                float* dst = &g_pooled[(size_t)s * HID + col0 + wn * 64];
#pragma unroll
                for (int nf = 0; nf < 8; nf++) {
                    atomicAdd(&dst[nf * 8 + ct * 2],
                              fmaxf(fr.acc[mf][nf][half * 2 + 0] + bb[nf][0], 0.f));
                    atomicAdd(&dst[nf * 8 + ct * 2 + 1],
                              fmaxf(fr.acc[mf][nf][half * 2 + 1] + bb[nf][1], 0.f));
                }
            } else if (mode == 1) {
                float* dst = &out_p[(size_t)r * D_OUTK + (col0 - HID) + wn * 64];
#pragma unroll
                for (int nf = 0; nf < 8; nf++) {
                    float2 o;
                    o.x = fmaxf(fr.acc[mf][nf][half * 2 + 0] + bb[nf][0], 0.f);
                    o.y = fmaxf(fr.acc[mf][nf][half * 2 + 1] + bb[nf][1], 0.f);
                    *(float2*)&dst[nf * 8 + ct * 2] = o;
                }
            } else {
                int o = edges[2 * r + 1];
                float* dst = &g_pooled[(size_t)o * HID + (col0 - HID - D_OUTK) + wn * 64];
#pragma unroll
                for (int nf = 0; nf < 8; nf++) {
                    atomicAdd(&dst[nf * 8 + ct * 2],
                              fmaxf(fr.acc[mf][nf][half * 2 + 0] + bb[nf][0], 0.f));
                    atomicAdd(&dst[nf * 8 + ct * 2 + 1],
                              fmaxf(fr.acc[mf][nf][half * 2 + 1] + bb[nf][1], 0.f));
                }
            }
        }
}

// ---------------------------------------------------------------------------
// stage 0: tmp     = relu((pooled / max(counts,1)) @ W3 + b3)   N=512
// stage 1: new_obj = relu(tmp @ W4 + b4)                        N=128
__global__ __launch_bounds__(256) void gemm_plain(
    const float* __restrict__ Bmat, const float* __restrict__ bias,
    float* __restrict__ Cout, int M, int N, int stage)
{
    const int K = HID;
    __shared__ uint32_t As[BM * APITCH];
    __shared__ uint32_t Bs[BK * BPITCH];

    int tid = threadIdx.x, lane = tid & 31, w = tid >> 5;
    int wm = w & 3, wn = w >> 2;
    int gr = lane >> 2, ct = lane & 3;
    int row0 = blockIdx.y * BM, col0 = blockIdx.x * BN;

    const float* A = (stage == 0) ? g_pooled : g_tmp;
    float* C = (stage == 0) ? g_tmp : Cout;

    Frag fr; fr.clear();

    for (int k0 = 0; k0 < K; k0 += BK) {
#pragma unroll
        for (int i = 0; i < 4; ++i) {
            int f = tid + i * 256;
            int m = f >> 3, k4 = (f & 7) << 2;
            int mg = row0 + m;
            float4 v = make_float4(0.f, 0.f, 0.f, 0.f);
            if (mg < M) {
                v = *(const float4*)&A[(size_t)mg * K + k0 + k4];
                if (stage == 0) {
                    float sc = 1.f / fmaxf(g_counts[mg], 1.f);
                    v.x *= sc; v.y *= sc; v.z *= sc; v.w *= sc;
                }
            }
            *(uint4*)&As[(size_t)m * APITCH + k4] = f4_to_tf32(v);
        }
#pragma unroll
        for (int i = 0; i < 4; ++i) {
            int f = tid + i * 256;
            int kk = f >> 5, n4 = (f & 31) << 2;
            float4 v = *(const float4*)&Bmat[(size_t)(k0 + kk) * N + col0 + n4];
            *(uint4*)&Bs[(size_t)kk * BPITCH + n4] = f4_to_tf32(v);
        }
        __syncthreads();
        mma_tile(fr, As, Bs, wm, wn, lane);
        __syncthreads();
    }

    float bb[8][2];
#pragma unroll
    for (int nf = 0; nf < 8; nf++) {
        int c = col0 + wn * 64 + nf * 8 + ct * 2;
        bb[nf][0] = bias[c]; bb[nf][1] = bias[c + 1];
    }
#pragma unroll
    for (int mf = 0; mf < 2; mf++)
#pragma unroll
        for (int half = 0; half < 2; half++) {
            int r = row0 + wm * 32 + mf * 16 + gr + half * 8;
            if (r >= M) continue;
            float* dst = &C[(size_t)r * N + col0 + wn * 64];
#pragma unroll
            for (int nf = 0; nf < 8; nf++) {
                float2 o;
                o.x = fmaxf(fr.acc[mf][nf][half * 2 + 0] + bb[nf][0], 0.f);
                o.y = fmaxf(fr.acc[mf][nf][half * 2 + 1] + bb[nf][1], 0.f);
                *(float2*)&dst[nf * 8 + ct * 2] = o;
            }
        }
}

// ---------------------------------------------------------------------------
extern "C" void kernel_launch(void* const* d_in, const int* in_sizes, int n_in,
                              void* d_out, int out_size)
{
    const float* obj   = (const float*)d_in[0];
    const float* pred  = (const float*)d_in[1];
    const int*   edges = (const int*)  d_in[2];
    const float* W1 = (const float*)d_in[3];
    const float* b1 = (const float*)d_in[4];
    const float* W2 = (const float*)d_in[5];
    const float* b2 = (const float*)d_in[6];
    const float* W3 = (const float*)d_in[7];
    const float* b3 = (const float*)d_in[8];
    const float* W4 = (const float*)d_in[9];
    const float* b4 = (const float*)d_in[10];

    float* out     = (float*)d_out;
    float* out_obj = out;                           // (NOBJ, 128)
    float* out_p   = out + (size_t)NOBJ * D_OUTK;   // (NT, 128)

    int gy_t = (NT + BM - 1) / BM;   // 1563
    int gy_o = (NOBJ + BM - 1) / BM; // 782

    zero_kernel<<<(NOBJ * HID / 4 + 255) / 256, 256>>>();
    count_kernel<<<(NT + 255) / 256, 256>>>(edges);
    gemm1_gather<<<dim3(HID / BN, gy_t), 256>>>(obj, pred, edges, W1, b1, NT);
    gemm2_scatter<<<dim3((2 * HID + D_OUTK) / BN, gy_t), 256>>>(W2, b2, edges, out_p, NT);
    gemm_plain<<<dim3(HID / BN, gy_o), 256>>>(W3, b3, nullptr, NOBJ, HID, 0);
    gemm_plain<<<dim3(D_OUTK / BN, gy_o), 256>>>(W4, b4, out_obj, NOBJ, D_OUTK, 1);
}

// round 3
// speedup vs baseline: 3.6069x; 1.3173x over previous
#include <cuda_runtime.h>
#include <cstdint>

#define D_IN   128
#define HID    512
#define D_OUTK 128
#define NOBJ   100000
#define NT     200000

#define BM 128
#define BN 128
#define BK 32
#define APITCH 36    // u32; bank = (4*gr+ct) -> conflict-free; 144B row, 16B aligned
#define BPITCH 136   // u32; bank = (8*ct+gr) -> conflict-free; 544B row, 16B aligned
#define ASZ (BM * APITCH)
#define BSZ (BK * BPITCH)
#define NSTAGE 3
#define SMEM_BYTES (NSTAGE * (ASZ + BSZ) * 4)

// Scratch (device globals — no allocation allowed)
__device__ __align__(16) float g_h[(size_t)NT * HID];         // tf32-rounded
__device__ __align__(16) float g_pooled[(size_t)NOBJ * HID];  // fp32 accum -> tf32 after normalize
__device__ __align__(16) float g_tmp[(size_t)NOBJ * HID];     // tf32-rounded
__device__ __align__(16) float g_counts[NOBJ];
// Pre-converted tf32 copies
__device__ __align__(16) float g_objt[(size_t)NOBJ * D_IN];
__device__ __align__(16) float g_predt[(size_t)NT * D_IN];
__device__ __align__(16) float g_W1t[3 * D_IN * HID];
__device__ __align__(16) float g_W2t[HID * (2 * HID + D_OUTK)];
__device__ __align__(16) float g_W3t[HID * HID];
__device__ __align__(16) float g_W4t[HID * D_OUTK];

// ---------------------------------------------------------------------------
__device__ __forceinline__ uint32_t f2tf32(float f) {
    uint32_t u;
    asm("cvt.rna.tf32.f32 %0, %1;" : "=r"(u) : "f"(f));
    return u;
}
__device__ __forceinline__ float tf32r(float f) { return __uint_as_float(f2tf32(f)); }

__device__ __forceinline__ void mma_tf32(float* c, const uint32_t* a, const uint32_t* b) {
    asm volatile(
        "mma.sync.aligned.m16n8k8.row.col.f32.tf32.tf32.f32 "
        "{%0,%1,%2,%3}, {%4,%5,%6,%7}, {%8,%9}, {%0,%1,%2,%3};"
        : "+f"(c[0]), "+f"(c[1]), "+f"(c[2]), "+f"(c[3])
        : "r"(a[0]), "r"(a[1]), "r"(a[2]), "r"(a[3]), "r"(b[0]), "r"(b[1]));
}

__device__ __forceinline__ void cp16(uint32_t smem_addr, const void* gsrc, int sz) {
    asm volatile("cp.async.cg.shared.global [%0], [%1], 16, %2;"
                 :: "r"(smem_addr), "l"(gsrc), "r"(sz));
}
#define CP_COMMIT() asm volatile("cp.async.commit_group;")
#define CP_WAIT1()  asm volatile("cp.async.wait_group 1;")

// ---------------------------------------------------------------------------
__global__ void zero_kernel() {
    int i = blockIdx.x * blockDim.x + threadIdx.x;
    float4 z = make_float4(0.f, 0.f, 0.f, 0.f);
    if (i < (NOBJ * HID) / 4) ((float4*)g_pooled)[i] = z;
    if (i < NOBJ / 4)         ((float4*)g_counts)[i] = z;
}

__global__ void count_kernel(const int* __restrict__ edges) {
    int t = blockIdx.x * blockDim.x + threadIdx.x;
    if (t < NT) {
        atomicAdd(&g_counts[edges[2 * t]],     1.f);
        atomicAdd(&g_counts[edges[2 * t + 1]], 1.f);
    }
}

__global__ void cvt_kernel(const float* __restrict__ src, float* __restrict__ dst, int n4) {
    int i = blockIdx.x * blockDim.x + threadIdx.x;
    if (i < n4) {
        float4 v = ((const float4*)src)[i];
        v.x = tf32r(v.x); v.y = tf32r(v.y); v.z = tf32r(v.z); v.w = tf32r(v.w);
        ((float4*)dst)[i] = v;
    }
}

// pooled[r][c] = tf32(pooled[r][c] / max(counts[r],1)), in place
__global__ void normalize_kernel() {
    int i = blockIdx.x * blockDim.x + threadIdx.x;
    if (i < (NOBJ * HID) / 4) {
        int r = i >> 7;  // HID/4 = 128
        float sc = 1.f / fmaxf(g_counts[r], 1.f);
        float4 v = ((const float4*)g_pooled)[i];
        v.x = tf32r(v.x * sc); v.y = tf32r(v.y * sc);
        v.z = tf32r(v.z * sc); v.w = tf32r(v.w * sc);
        ((float4*)g_pooled)[i] = v;
    }
}

// ---------------------------------------------------------------------------
struct Frag {
    float acc[2][8][4];
    __device__ __forceinline__ void clear() {
#pragma unroll
        for (int i = 0; i < 2; i++)
#pragma unroll
            for (int j = 0; j < 8; j++)
#pragma unroll
                for (int k = 0; k < 4; k++) acc[i][j][k] = 0.f;
    }
};

__device__ __forceinline__ void mma_stage(
    Frag& fr, const uint32_t* As, const uint32_t* Bs, int wm, int wn, int lane)
{
    int gr = lane >> 2, ct = lane & 3;
#pragma unroll
    for (int k8 = 0; k8 < BK; k8 += 8) {
        uint32_t a[2][4], b[8][2];
#pragma unroll
        for (int mf = 0; mf < 2; mf++) {
            int r = wm * 32 + mf * 16 + gr;
            a[mf][0] = As[r * APITCH + k8 + ct];
            a[mf][1] = As[(r + 8) * APITCH + k8 + ct];
            a[mf][2] = As[r * APITCH + k8 + ct + 4];
            a[mf][3] = As[(r + 8) * APITCH + k8 + ct + 4];
        }
#pragma unroll
        for (int nf = 0; nf < 8; nf++) {
            int n = wn * 64 + nf * 8 + gr;
            b[nf][0] = Bs[(k8 + ct) * BPITCH + n];
            b[nf][1] = Bs[(k8 + ct + 4) * BPITCH + n];
        }
#pragma unroll
        for (int mf = 0; mf < 2; mf++)
#pragma unroll
            for (int nf = 0; nf < 8; nf++)
                mma_tf32(fr.acc[mf][nf], a[mf], b[nf]);
    }
}

__device__ __forceinline__ void loadB_cp(
    uint32_t b_base, int stage, const float* __restrict__ W,
    int N, int k0, int col0, int tid)
{
#pragma unroll
    for (int i = 0; i < 4; ++i) {
        int f = tid + i * 256;
        int kk = f >> 5, n4 = (f & 31) << 2;
        cp16(b_base + (uint32_t)(stage * BSZ + kk * BPITCH + n4) * 4,
             W + (size_t)(k0 + kk) * N + col0 + n4, 16);
    }
}

__device__ __forceinline__ void loadA_cp(
    uint32_t a_base, int stage, const float* __restrict__ A,
    int K, int k0, int row0, int M, int tid)
{
#pragma unroll
    for (int i = 0; i < 4; ++i) {
        int f = tid + i * 256;
        int m = f >> 3, k4 = (f & 7) << 2;
        int mg = row0 + m;
        int mgc = mg < M ? mg : M - 1;
        cp16(a_base + (uint32_t)(stage * ASZ + m * APITCH + k4) * 4,
             A + (size_t)mgc * K + k0 + k4, mg < M ? 16 : 0);
    }
}

__device__ __forceinline__ void loadA_gather_cp(
    uint32_t a_base, int stage, const int* __restrict__ edges,
    int k0, int row0, int M, int tid)
{
#pragma unroll
    for (int i = 0; i < 4; ++i) {
        int f = tid + i * 256;
        int m = f >> 3, k4 = (f & 7) << 2;
        int mg = row0 + m;
        int mgc = mg < M ? mg : M - 1;
        int gk = k0 + k4;
        const float* src;
        if (gk < 128)      src = g_objt  + (size_t)edges[2 * mgc]     * 128 + gk;
        else if (gk < 256) src = g_predt + (size_t)mgc                * 128 + (gk - 128);
        else               src = g_objt  + (size_t)edges[2 * mgc + 1] * 128 + (gk - 256);
        cp16(a_base + (uint32_t)(stage * ASZ + m * APITCH + k4) * 4,
             src, mg < M ? 16 : 0);
    }
}

// ---------------------------------------------------------------------------
// GEMM1: g_h = tf32(relu(concat(objt[s], predt, objt[o]) @ W1t + b1))
__global__ __launch_bounds__(256, 2) void gemm1_gather(
    const int* __restrict__ edges, const float* __restrict__ b1, int M)
{
    const int K = 3 * D_IN, N = HID, KT = K / BK;
    extern __shared__ uint32_t smem[];
    uint32_t* Asm = smem;
    uint32_t* Bsm = smem + NSTAGE * ASZ;
    uint32_t a_base = (uint32_t)__cvta_generic_to_shared(Asm);
    uint32_t b_base = (uint32_t)__cvta_generic_to_shared(Bsm);

    int tid = threadIdx.x, lane = tid & 31, w = tid >> 5;
    int wm = w & 3, wn = w >> 2;
    int gr = lane >> 2, ct = lane & 3;
    int row0 = blockIdx.y * BM, col0 = blockIdx.x * BN;

    Frag fr; fr.clear();

    loadA_gather_cp(a_base, 0, edges, 0, row0, M, tid);
    loadB_cp(b_base, 0, g_W1t, N, 0, col0, tid);
    CP_COMMIT();
    loadA_gather_cp(a_base, 1, edges, BK, row0, M, tid);
    loadB_cp(b_base, 1, g_W1t, N, BK, col0, tid);
    CP_COMMIT();

    for (int kt = 0; kt < KT; kt++) {
        CP_WAIT1();
        __syncthreads();
        if (kt + 2 < KT) {
            int s = (kt + 2) % NSTAGE, k0 = (kt + 2) * BK;
            loadA_gather_cp(a_base, s, edges, k0, row0, M, tid);
            loadB_cp(b_base, s, g_W1t, N, k0, col0, tid);
        }
        CP_COMMIT();
        int s = kt % NSTAGE;
        mma_stage(fr, Asm + s * ASZ, Bsm + s * BSZ, wm, wn, lane);
    }

    float bb[8][2];
#pragma unroll
    for (int nf = 0; nf < 8; nf++) {
        int c = col0 + wn * 64 + nf * 8 + ct * 2;
        bb[nf][0] = b1[c]; bb[nf][1] = b1[c + 1];
    }
#pragma unroll
    for (int mf = 0; mf < 2; mf++)
#pragma unroll
        for (int half = 0; half < 2; half++) {
            int r = row0 + wm * 32 + mf * 16 + gr + half * 8;
            if (r >= M) continue;
            float* dst = &g_h[(size_t)r * HID + col0 + wn * 64];
#pragma unroll
            for (int nf = 0; nf < 8; nf++) {
                float2 o;
                o.x = tf32r(fmaxf(fr.acc[mf][nf][half * 2 + 0] + bb[nf][0], 0.f));
                o.y = tf32r(fmaxf(fr.acc[mf][nf][half * 2 + 1] + bb[nf][1], 0.f));
                *(float2*)&dst[nf * 8 + ct * 2] = o;
            }
        }
}

// ---------------------------------------------------------------------------
// GEMM2: new_t = relu(g_h @ W2t + b2).  N=1152.
// cols [0,512): atomicAdd -> pooled[s]; [512,640): new_p; [640,1152): pooled[o]
__global__ __launch_bounds__(256, 2) void gemm2_scatter(
    const int* __restrict__ edges, const float* __restrict__ b2,
    float* __restrict__ out_p, int M)
{
    const int K = HID, N = 2 * HID + D_OUTK, KT = K / BK;
    extern __shared__ uint32_t smem[];
    uint32_t* Asm = smem;
    uint32_t* Bsm = smem + NSTAGE * ASZ;
    uint32_t a_base = (uint32_t)__cvta_generic_to_shared(Asm);
    uint32_t b_base = (uint32_t)__cvta_generic_to_shared(Bsm);

    int tid = threadIdx.x, lane = tid & 31, w = tid >> 5;
    int wm = w & 3, wn = w >> 2;
    int gr = lane >> 2, ct = lane & 3;
    int row0 = blockIdx.y * BM, col0 = blockIdx.x * BN;

    Frag fr; fr.clear();

    loadA_cp(a_base, 0, g_h, K, 0, row0, M, tid);
    loadB_cp(b_base, 0, g_W2t, N, 0, col0, tid);
    CP_COMMIT();
    loadA_cp(a_base, 1, g_h, K, BK, row0, M, tid);
    loadB_cp(b_base, 1, g_W2t, N, BK, col0, tid);
    CP_COMMIT();

    for (int kt = 0; kt < KT; kt++) {
        CP_WAIT1();
        __syncthreads();
        if (kt + 2 < KT) {
            int s = (kt + 2) % NSTAGE, k0 = (kt + 2) * BK;
            loadA_cp(a_base, s, g_h, K, k0, row0, M, tid);
            loadB_cp(b_base, s, g_W2t, N, k0, col0, tid);
        }
        CP_COMMIT();
        int s = kt % NSTAGE;
        mma_stage(fr, Asm + s * ASZ, Bsm + s * BSZ, wm, wn, lane);
    }

    float bb[8][2];
#pragma unroll
    for (int nf = 0; nf < 8; nf++) {
        int c = col0 + wn * 64 + nf * 8 + ct * 2;
        bb[nf][0] = b2[c]; bb[nf][1] = b2[c + 1];
    }

    int mode = (col0 < HID) ? 0 : ((col0 < HID + D_OUTK) ? 1 : 2);

#pragma unroll
    for (int mf = 0; mf < 2; mf++)
#pragma unroll
        for (int half = 0; half < 2; half++) {
            int r = row0 + wm * 32 + mf * 16 + gr + half * 8;
            if (r >= M) continue;
            if (mode == 0) {
                int s = edges[2 * r];
                float* dst = &g_pooled[(size_t)s * HID + col0 + wn * 64];
#pragma unroll
                for (int nf = 0; nf < 8; nf++) {
                    atomicAdd(&dst[nf * 8 + ct * 2],
                              fmaxf(fr.acc[mf][nf][half * 2 + 0] + bb[nf][0], 0.f));
                    atomicAdd(&dst[nf * 8 + ct * 2 + 1],
                              fmaxf(fr.acc[mf][nf][half * 2 + 1] + bb[nf][1], 0.f));
                }
            } else if (mode == 1) {
                float* dst = &out_p[(size_t)r * D_OUTK + (col0 - HID) + wn * 64];
#pragma unroll
                for (int nf = 0; nf < 8; nf++) {
                    float2 o;
                    o.x = fmaxf(fr.acc[mf][nf][half * 2 + 0] + bb[nf][0], 0.f);
                    o.y = fmaxf(fr.acc[mf][nf][half * 2 + 1] + bb[nf][1], 0.f);
                    *(float2*)&dst[nf * 8 + ct * 2] = o;
                }
            } else {
                int o = edges[2 * r + 1];
                float* dst = &g_pooled[(size_t)o * HID + (col0 - HID - D_OUTK) + wn * 64];
#pragma unroll
                for (int nf = 0; nf < 8; nf++) {
                    atomicAdd(&dst[nf * 8 + ct * 2],
                              fmaxf(fr.acc[mf][nf][half * 2 + 0] + bb[nf][0], 0.f));
                    atomicAdd(&dst[nf * 8 + ct * 2 + 1],
                              fmaxf(fr.acc[mf][nf][half * 2 + 1] + bb[nf][1], 0.f));
                }
            }
        }
}

// ---------------------------------------------------------------------------
// stage 0: g_tmp   = tf32(relu(g_pooled @ W3t + b3))   N=512  (pooled pre-normalized)
// stage 1: new_obj = relu(g_tmp @ W4t + b4)            N=128
__global__ __launch_bounds__(256, 2) void gemm_plain(
    const float* __restrict__ bias, float* __restrict__ Cout,
    int M, int N, int stage)
{
    const int K = HID, KT = K / BK;
    extern __shared__ uint32_t smem[];
    uint32_t* Asm = smem;
    uint32_t* Bsm = smem + NSTAGE * ASZ;
    uint32_t a_base = (uint32_t)__cvta_generic_to_shared(Asm);
    uint32_t b_base = (uint32_t)__cvta_generic_to_shared(Bsm);

    int tid = threadIdx.x, lane = tid & 31, w = tid >> 5;
    int wm = w & 3, wn = w >> 2;
    int gr = lane >> 2, ct = lane & 3;
    int row0 = blockIdx.y * BM, col0 = blockIdx.x * BN;

    const float* A = (stage == 0) ? g_pooled : g_tmp;
    const float* W = (stage == 0) ? g_W3t : g_W4t;
    float* C = (stage == 0) ? g_tmp : Cout;

    Frag fr; fr.clear();

    loadA_cp(a_base, 0, A, K, 0, row0, M, tid);
    loadB_cp(b_base, 0, W, N, 0, col0, tid);
    CP_COMMIT();
    loadA_cp(a_base, 1, A, K, BK, row0, M, tid);
    loadB_cp(b_base, 1, W, N, BK, col0, tid);
    CP_COMMIT();

    for (int kt = 0; kt < KT; kt++) {
        CP_WAIT1();
        __syncthreads();
        if (kt + 2 < KT) {
            int s = (kt + 2) % NSTAGE, k0 = (kt + 2) * BK;
            loadA_cp(a_base, s, A, K, k0, row0, M, tid);
            loadB_cp(b_base, s, W, N, k0, col0, tid);
        }
        CP_COMMIT();
        int s = kt % NSTAGE;
        mma_stage(fr, Asm + s * ASZ, Bsm + s * BSZ, wm, wn, lane);
    }

    float bb[8][2];
#pragma unroll
    for (int nf = 0; nf < 8; nf++) {
        int c = col0 + wn * 64 + nf * 8 + ct * 2;
        bb[nf][0] = bias[c]; bb[nf][1] = bias[c + 1];
    }
#pragma unroll
    for (int mf = 0; mf < 2; mf++)
#pragma unroll
        for (int half = 0; half < 2; half++) {
            int r = row0 + wm * 32 + mf * 16 + gr + half * 8;
            if (r >= M) continue;
            float* dst = &C[(size_t)r * N + col0 + wn * 64];
#pragma unroll
            for (int nf = 0; nf < 8; nf++) {
                float2 o;
                o.x = fmaxf(fr.acc[mf][nf][half * 2 + 0] + bb[nf][0], 0.f);
                o.y = fmaxf(fr.acc[mf][nf][half * 2 + 1] + bb[nf][1], 0.f);
                if (stage == 0) { o.x = tf32r(o.x); o.y = tf32r(o.y); }
                *(float2*)&dst[nf * 8 + ct * 2] = o;
            }
        }
}

// ---------------------------------------------------------------------------
extern "C" void kernel_launch(void* const* d_in, const int* in_sizes, int n_in,
                              void* d_out, int out_size)
{
    const float* obj   = (const float*)d_in[0];
    const float* pred  = (const float*)d_in[1];
    const int*   edges = (const int*)  d_in[2];
    const float* b1 = (const float*)d_in[4];
    const float* b2 = (const float*)d_in[6];
    const float* b3 = (const float*)d_in[8];
    const float* b4 = (const float*)d_in[10];
    const float* W1 = (const float*)d_in[3];
    const float* W2 = (const float*)d_in[5];
    const float* W3 = (const float*)d_in[7];
    const float* W4 = (const float*)d_in[9];

    float* out     = (float*)d_out;
    float* out_obj = out;                           // (NOBJ, 128)
    float* out_p   = out + (size_t)NOBJ * D_OUTK;   // (NT, 128)

    cudaFuncSetAttribute(gemm1_gather,  cudaFuncAttributeMaxDynamicSharedMemorySize, SMEM_BYTES);
    cudaFuncSetAttribute(gemm2_scatter, cudaFuncAttributeMaxDynamicSharedMemorySize, SMEM_BYTES);
    cudaFuncSetAttribute(gemm_plain,    cudaFuncAttributeMaxDynamicSharedMemorySize, SMEM_BYTES);

    int gy_t = (NT + BM - 1) / BM;   // 1563
    int gy_o = (NOBJ + BM - 1) / BM; // 782

    // scratch prep + tf32 preconversion
    zero_kernel<<<(NOBJ * HID / 4 + 255) / 256, 256>>>();
    count_kernel<<<(NT + 255) / 256, 256>>>(edges);

    float* g_objt_p;  cudaGetSymbolAddress((void**)&g_objt_p,  g_objt);
    float* g_predt_p; cudaGetSymbolAddress((void**)&g_predt_p, g_predt);
    float* g_W1t_p;   cudaGetSymbolAddress((void**)&g_W1t_p,   g_W1t);
    float* g_W2t_p;   cudaGetSymbolAddress((void**)&g_W2t_p,   g_W2t);
    float* g_W3t_p;   cudaGetSymbolAddress((void**)&g_W3t_p,   g_W3t);
    float* g_W4t_p;   cudaGetSymbolAddress((void**)&g_W4t_p,   g_W4t);

    auto cvt = [](const float* s, float* d, long n) {
        int n4 = (int)(n / 4);
        cvt_kernel<<<(n4 + 255) / 256, 256>>>(s, d, n4);
    };
    cvt(obj,  g_objt_p,  (long)NOBJ * D_IN);
    cvt(pred, g_predt_p, (long)NT * D_IN);
    cvt(W1, g_W1t_p, (long)3 * D_IN * HID);
    cvt(W2, g_W2t_p, (long)HID * (2 * HID + D_OUTK));
    cvt(W3, g_W3t_p, (long)HID * HID);
    cvt(W4, g_W4t_p, (long)HID * D_OUTK);

    gemm1_gather<<<dim3(HID / BN, gy_t), 256, SMEM_BYTES>>>(edges, b1, NT);
    gemm2_scatter<<<dim3((2 * HID + D_OUTK) / BN, gy_t), 256, SMEM_BYTES>>>(edges, b2, out_p, NT);
    normalize_kernel<<<(NOBJ * HID / 4 + 255) / 256, 256>>>();
    gemm_plain<<<dim3(HID / BN, gy_o), 256, SMEM_BYTES>>>(b3, nullptr, NOBJ, HID, 0);
    gemm_plain<<<dim3(D_OUTK / BN, gy_o), 256, SMEM_BYTES>>>(b4, out_obj, NOBJ, D_OUTK, 1);
}

// round 5
// speedup vs baseline: 6.5748x; 1.8228x over previous
#include <cuda_runtime.h>
#include <cuda_fp16.h>
#include <cstdint>

#define D_IN   128
#define HID    512
#define D_OUTK 128
#define NOBJ   100000
#define NT     200000

#define BM 128
#define BN 128
#define BK 64                      // halfs per stage-chunk (128 B per row)
#define A_BYTES (BM * BK * 2)      // 16 KB
#define STAGE_BYTES (2 * A_BYTES)  // A + B = 32 KB
#define NSTAGE 3
#define SMEMB (NSTAGE * STAGE_BYTES)

// Scratch (device globals — no allocation allowed)
__device__ __align__(16) __half g_h[(size_t)NT * HID];
__device__ __align__(16) float  g_pooled[(size_t)NOBJ * HID];
__device__ __align__(16) __half g_pooledh[(size_t)NOBJ * HID];
__device__ __align__(16) __half g_tmph[(size_t)NOBJ * HID];
__device__ __align__(16) float  g_counts[NOBJ];
__device__ __align__(16) __half g_objth[(size_t)NOBJ * D_IN];
__device__ __align__(16) __half g_predth[(size_t)NT * D_IN];
// Weights transposed to [n][k], fp16
__device__ __align__(16) __half g_W1T[(size_t)HID * 384];
__device__ __align__(16) __half g_W2T[(size_t)1152 * HID];
__device__ __align__(16) __half g_W3T[(size_t)HID * HID];
__device__ __align__(16) __half g_W4T[(size_t)D_OUTK * HID];

// ---------------------------------------------------------------------------
__device__ __forceinline__ void mma_f16(float* c, const uint32_t* a, const uint32_t* b) {
    asm volatile(
        "mma.sync.aligned.m16n8k16.row.col.f32.f16.f16.f32 "
        "{%0,%1,%2,%3}, {%4,%5,%6,%7}, {%8,%9}, {%0,%1,%2,%3};"
        : "+f"(c[0]), "+f"(c[1]), "+f"(c[2]), "+f"(c[3])
        : "r"(a[0]), "r"(a[1]), "r"(a[2]), "r"(a[3]), "r"(b[0]), "r"(b[1]));
}

__device__ __forceinline__ void cp16(uint32_t d, const void* s, int sz) {
    asm volatile("cp.async.cg.shared.global [%0], [%1], 16, %2;"
                 :: "r"(d), "l"(s), "r"(sz));
}
#define CP_COMMIT() asm volatile("cp.async.commit_group;" ::: "memory")
#define CP_WAIT1()  asm volatile("cp.async.wait_group 1;" ::: "memory")

__device__ __forceinline__ uint32_t lds32(uint32_t addr) {
    uint32_t v;
    asm volatile("ld.shared.b32 %0, [%1];" : "=r"(v) : "r"(addr));
    return v;
}

// ---------------------------------------------------------------------------
__global__ void zero_kernel() {
    int i = blockIdx.x * blockDim.x + threadIdx.x;
    float4 z = make_float4(0.f, 0.f, 0.f, 0.f);
    if (i < (NOBJ * HID) / 4) ((float4*)g_pooled)[i] = z;
    if (i < NOBJ / 4)         ((float4*)g_counts)[i] = z;
}

__global__ void count_kernel(const int* __restrict__ edges) {
    int t = blockIdx.x * blockDim.x + threadIdx.x;
    if (t < NT) {
        atomicAdd(&g_counts[edges[2 * t]],     1.f);
        atomicAdd(&g_counts[edges[2 * t + 1]], 1.f);
    }
}

__global__ void cvt_h(const float* __restrict__ src, __half* __restrict__ dst, int n4) {
    int i = blockIdx.x * blockDim.x + threadIdx.x;
    if (i < n4) {
        float4 v = ((const float4*)src)[i];
        __half2* d2 = (__half2*)dst;
        d2[2 * i]     = __floats2half2_rn(v.x, v.y);
        d2[2 * i + 1] = __floats2half2_rn(v.z, v.w);
    }
}

// WT[n][k] = half(W[k][n])
__global__ void cvtT_h(const float* __restrict__ W, __half* __restrict__ WT, int K, int N) {
    int idx = blockIdx.x * blockDim.x + threadIdx.x;
    if (idx < N * K) {
        int n = idx / K, k = idx - n * K;
        WT[idx] = __float2half_rn(W[(size_t)k * N + n]);
    }
}

// pooledh[r][c] = half(pooled[r][c] / max(counts[r],1))
__global__ void normalize_h() {
    int i = blockIdx.x * blockDim.x + threadIdx.x;
    if (i < (NOBJ * HID) / 4) {
        int r = i >> 7;
        float sc = 1.f / fmaxf(g_counts[r], 1.f);
        float4 v = ((const float4*)g_pooled)[i];
        __half2* d2 = (__half2*)g_pooledh;
        d2[2 * i]     = __floats2half2_rn(v.x * sc, v.y * sc);
        d2[2 * i + 1] = __floats2half2_rn(v.z * sc, v.w * sc);
    }
}

// ---------------------------------------------------------------------------
// KIND 0: g_h    = h(relu(gather @ W1T + b1))        M=NT,   K=384, N=512
// KIND 1: scatter/out_p from relu(g_h @ W2T + b2)    M=NT,   K=512, N=1152
// KIND 2: g_tmph = h(relu(pooledh @ W3T + b3))       M=NOBJ, K=512, N=512
// KIND 3: out_obj = relu(g_tmph @ W4T + b4)          M=NOBJ, K=512, N=128
template<int KIND>
__global__ void __launch_bounds__(256, 2) hgemm(const int* __restrict__ edges,
                                                const float* __restrict__ bias,
                                                float* __restrict__ out, int M)
{
    constexpr int K  = (KIND == 0) ? 384 : 512;
    constexpr int KT = K / BK;
    extern __shared__ __align__(16) char sh[];
    uint32_t sm = (uint32_t)__cvta_generic_to_shared(sh);

    int tid = threadIdx.x, lane = tid & 31, w = tid >> 5;
    int wm = w & 3, wn = w >> 2;                 // 4 (m) x 2 (n) warps
    int gr = lane >> 2, ct = lane & 3;
    int row0 = blockIdx.y * BM;
    int col0 = blockIdx.x * BN;

    int mode = 0, pcol = 0;                      // KIND 1 column routing
    if (KIND == 1) {
        int bx = blockIdx.x;
        if (bx < 4)       { mode = 0; pcol = bx * 128; }
        else if (bx == 4) { mode = 1; pcol = 0; }
        else              { mode = 2; pcol = (bx - 5) * 128; }
    }

    const __half* Wt   = (KIND == 0) ? g_W1T : (KIND == 1) ? g_W2T
                       : (KIND == 2) ? g_W3T : g_W4T;
    const __half* Amat = (KIND == 1) ? g_h : (KIND == 2) ? g_pooledh : g_tmph;

    float acc[2][8][4];
#pragma unroll
    for (int i = 0; i < 2; i++)
#pragma unroll
        for (int j = 0; j < 8; j++)
#pragma unroll
            for (int k = 0; k < 4; k++) acc[i][j][k] = 0.f;

    auto load_stage = [&](int kt) {
        int k0 = kt * BK;                          // in halfs
        uint32_t ab = sm + (uint32_t)(kt % NSTAGE) * STAGE_BYTES;
        uint32_t bb = ab + A_BYTES;
#pragma unroll
        for (int i = 0; i < 4; i++) {              // A: 128 rows x 8 chunks
            int f = tid + i * 256;
            int m = f >> 3, ch = f & 7;
            int mg = row0 + m;
            int sz = (mg < M) ? 16 : 0;
            int mc = (mg < M) ? mg : M - 1;
            const char* src;
            if (KIND == 0) {
                int region = k0 >> 7;
                int bo = (k0 & 127) * 2;
                if (region == 0)      src = (const char*)(g_objth  + (size_t)edges[2 * mc]     * 128) + bo;
                else if (region == 1) src = (const char*)(g_predth + (size_t)mc                * 128) + bo;
                else                  src = (const char*)(g_objth  + (size_t)edges[2 * mc + 1] * 128) + bo;
            } else {
                src = (const char*)(Amat + (size_t)mc * K + k0);
            }
            cp16(ab + (uint32_t)(m * 128 + ((ch ^ (m & 7)) * 16)), src + ch * 16, sz);
        }
#pragma unroll
        for (int i = 0; i < 4; i++) {              // B: 128 n-rows x 8 chunks
            int f = tid + i * 256;
            int n = f >> 3, ch = f & 7;
            const char* src = (const char*)(Wt + (size_t)(col0 + n) * K + k0) + ch * 16;
            cp16(bb + (uint32_t)(n * 128 + ((ch ^ (n & 7)) * 16)), src, 16);
        }
    };

    auto mma_stage = [&](int b) {
        uint32_t abase = sm + (uint32_t)b * STAGE_BYTES;
        uint32_t bbase = abase + A_BYTES;
#pragma unroll
        for (int kb = 0; kb < BK / 16; kb++) {
            uint32_t c0 = (uint32_t)(((2 * kb)     ^ gr) * 16 + ct * 4);
            uint32_t c1 = (uint32_t)(((2 * kb + 1) ^ gr) * 16 + ct * 4);
            uint32_t a[2][4], bf[8][2];
#pragma unroll
            for (int mf = 0; mf < 2; mf++) {
                uint32_t r = (uint32_t)(wm * 32 + mf * 16 + gr);
                a[mf][0] = lds32(abase + r * 128 + c0);
                a[mf][1] = lds32(abase + (r + 8) * 128 + c0);
                a[mf][2] = lds32(abase + r * 128 + c1);
                a[mf][3] = lds32(abase + (r + 8) * 128 + c1);
            }
#pragma unroll
            for (int nf = 0; nf < 8; nf++) {
                uint32_t n = (uint32_t)(wn * 64 + nf * 8 + gr);
                bf[nf][0] = lds32(bbase + n * 128 + c0);
                bf[nf][1] = lds32(bbase + n * 128 + c1);
            }
#pragma unroll
            for (int mf = 0; mf < 2; mf++)
#pragma unroll
                for (int nf = 0; nf < 8; nf++)
                    mma_f16(acc[mf][nf], a[mf], bf[nf]);
        }
    };

    load_stage(0); CP_COMMIT();
    load_stage(1); CP_COMMIT();

    for (int kt = 0; kt < KT; kt++) {
        CP_WAIT1();
        __syncthreads();
        if (kt + 2 < KT) load_stage(kt + 2);
        CP_COMMIT();
        mma_stage(kt % NSTAGE);
    }

    // ---- epilogue ----
    float bb[8][2];
#pragma unroll
    for (int nf = 0; nf < 8; nf++) {
        int c = col0 + wn * 64 + nf * 8 + ct * 2;
        bb[nf][0] = bias[c]; bb[nf][1] = bias[c + 1];
    }

#pragma unroll
    for (int mf = 0; mf < 2; mf++)
#pragma unroll
        for (int half = 0; half < 2; half++) {
            int r = row0 + wm * 32 + mf * 16 + gr + half * 8;
            if (r >= M) continue;
            int cbase = wn * 64 + ct * 2;
            if (KIND == 0 || KIND == 2) {
                __half* dst = ((KIND == 0) ? g_h : g_tmph) + (size_t)r * HID + col0 + cbase;
#pragma unroll
                for (int nf = 0; nf < 8; nf++) {
                    float x = fmaxf(acc[mf][nf][half * 2 + 0] + bb[nf][0], 0.f);
                    float y = fmaxf(acc[mf][nf][half * 2 + 1] + bb[nf][1], 0.f);
                    *(__half2*)(dst + nf * 8) = __floats2half2_rn(x, y);
                }
            } else if (KIND == 3) {
                float* dst = out + (size_t)r * D_OUTK + cbase;
#pragma unroll
                for (int nf = 0; nf < 8; nf++) {
                    float2 o;
                    o.x = fmaxf(acc[mf][nf][half * 2 + 0] + bb[nf][0], 0.f);
                    o.y = fmaxf(acc[mf][nf][half * 2 + 1] + bb[nf][1], 0.f);
                    *(float2*)(dst + nf * 8) = o;
                }
            } else {  // KIND == 1
                if (mode == 1) {
                    float* dst = out + (size_t)r * D_OUTK + cbase;
#pragma unroll
                    for (int nf = 0; nf < 8; nf++) {
                        float2 o;
                        o.x = fmaxf(acc[mf][nf][half * 2 + 0] + bb[nf][0], 0.f);
                        o.y = fmaxf(acc[mf][nf][half * 2 + 1] + bb[nf][1], 0.f);
                        *(float2*)(dst + nf * 8) = o;
                    }
                } else {
                    int sidx = (mode == 0) ? edges[2 * r] : edges[2 * r + 1];
                    float* dst = g_pooled + (size_t)sidx * HID + pcol + cbase;
#pragma unroll
                    for (int nf = 0; nf < 8; nf++) {
                        atomicAdd(dst + nf * 8,
                                  fmaxf(acc[mf][nf][half * 2 + 0] + bb[nf][0], 0.f));
                        atomicAdd(dst + nf * 8 + 1,
                                  fmaxf(acc[mf][nf][half * 2 + 1] + bb[nf][1], 0.f));
                    }
                }
            }
        }
}

// ---------------------------------------------------------------------------
extern "C" void kernel_launch(void* const* d_in, const int* in_sizes, int n_in,
                              void* d_out, int out_size)
{
    const float* obj   = (const float*)d_in[0];
    const float* pred  = (const float*)d_in[1];
    const int*   edges = (const int*)  d_in[2];
    const float* W1 = (const float*)d_in[3];
    const float* b1 = (const float*)d_in[4];
    const float* W2 = (const float*)d_in[5];
    const float* b2 = (const float*)d_in[6];
    const float* W3 = (const float*)d_in[7];
    const float* b3 = (const float*)d_in[8];
    const float* W4 = (const float*)d_in[9];
    const float* b4 = (const float*)d_in[10];

    float* out     = (float*)d_out;
    float* out_obj = out;                           // (NOBJ, 128)
    float* out_p   = out + (size_t)NOBJ * D_OUTK;   // (NT, 128)

    cudaFuncSetAttribute(hgemm<0>, cudaFuncAttributeMaxDynamicSharedMemorySize, SMEMB);
    cudaFuncSetAttribute(hgemm<1>, cudaFuncAttributeMaxDynamicSharedMemorySize, SMEMB);
    cudaFuncSetAttribute(hgemm<2>, cudaFuncAttributeMaxDynamicSharedMemorySize, SMEMB);
    cudaFuncSetAttribute(hgemm<3>, cudaFuncAttributeMaxDynamicSharedMemorySize, SMEMB);

    __half *p_objth, *p_predth, *p_W1T, *p_W2T, *p_W3T, *p_W4T;
    cudaGetSymbolAddress((void**)&p_objth,  g_objth);
    cudaGetSymbolAddress((void**)&p_predth, g_predth);
    cudaGetSymbolAddress((void**)&p_W1T,    g_W1T);
    cudaGetSymbolAddress((void**)&p_W2T,    g_W2T);
    cudaGetSymbolAddress((void**)&p_W3T,    g_W3T);
    cudaGetSymbolAddress((void**)&p_W4T,    g_W4T);

    zero_kernel<<<(NOBJ * HID / 4 + 255) / 256, 256>>>();
    count_kernel<<<(NT + 255) / 256, 256>>>(edges);

    {
        int n4 = NOBJ * D_IN / 4;
        cvt_h<<<(n4 + 255) / 256, 256>>>(obj, p_objth, n4);
    }
    {
        int n4 = NT * D_IN / 4;
        cvt_h<<<(n4 + 255) / 256, 256>>>(pred, p_predth, n4);
    }
    auto cvtT = [](const float* s, __half* d, int K, int N) {
        int n = K * N;
        cvtT_h<<<(n + 255) / 256, 256>>>(s, d, K, N);
    };
    cvtT(W1, p_W1T, 384, 512);
    cvtT(W2, p_W2T, 512, 1152);
    cvtT(W3, p_W3T, 512, 512);
    cvtT(W4, p_W4T, 512, 128);

    int gy_t = (NT + BM - 1) / BM;    // 1563
    int gy_o = (NOBJ + BM - 1) / BM;  // 782

    hgemm<0><<<dim3(4, gy_t), 256, SMEMB>>>(edges, b1, nullptr, NT);
    hgemm<1><<<dim3(9, gy_t), 256, SMEMB>>>(edges, b2, out_p, NT);
    normalize_h<<<(NOBJ * HID / 4 + 255) / 256, 256>>>();
    hgemm<2><<<dim3(4, gy_o), 256, SMEMB>>>(edges, b3, nullptr, NOBJ);
    hgemm<3><<<dim3(1, gy_o), 256, SMEMB>>>(edges, b4, out_obj, NOBJ);
}